// round 10
// baseline (speedup 1.0000x reference)
#include <cuda_runtime.h>
#include <math.h>

#define NPIX 262144      // 16*128*128
#define DIMD 64
#define KC   1024
#define NFINE 8192
#define NBLK 128
#define FPC   (NFINE / NBLK)         // 64 fine cells per block
#define XLO  (-12.0)
#define XRNG (24.0)
#define FWID (XRNG / (double)NFINE)
#define CWID (XRNG / (double)NBLK)
#define PADX (1e-4)
#define EPSM (1e-4f)
#define CCAP 64
#define FCAP 8

// ---- scratch (__device__ globals; zero-initialized at module load) ----
__device__ double d_m[KC], d_g[KC];
__device__ float  d_mf[KC], d_gf[KC];
__device__ float  d_of[KC];
__device__ float  d_Swf, d_Swbf, d_Sbf;
__device__ int    d_cand[NFINE * FCAP];
__device__ float4 d_fast[NFINE];             // (m, g, o, cnt-as-int)
__device__ double d_bsum[NBLK];
// Monotone ticket counters — NEVER reset. Each launch consumes the next
// range of NBLK tickets; no cross-replay state restoration required.
__device__ unsigned d_t1, d_t2, d_t3;

__device__ __forceinline__ void grid_barrier_mono(unsigned* ctr) {
    __syncthreads();
    if (threadIdx.x == 0) {
        __threadfence();
        unsigned old = atomicAdd(ctr, 1);
        unsigned target = old - (old % NBLK) + NBLK;   // next multiple of NBLK
        while (*(volatile unsigned*)ctr < target) __nanosleep(64);
        __threadfence();
    }
    __syncthreads();
}

__device__ double wedge_peak(int c0, int c1, double xa, double xb) {
    double m0 = d_m[c0], g0 = d_g[c0];
    double m1 = d_m[c1], g1 = d_g[c1];
    double wa = fmin(fma(m0, xa, g0), fma(m1, xa, g1));
    double wb = fmin(fma(m0, xb, g0), fma(m1, xb, g1));
    double pk = fmax(wa, wb);
    if (m0 != m1) {
        double xc = (g1 - g0) / (m0 - m1);
        if (xc > xa && xc < xb) pk = fmax(pk, fma(m0, xc, g0));
    }
    return pk;
}

// ================= single fused kernel =================
__global__ void __launch_bounds__(256, 2) kAll(const float* __restrict__ emb,
                                               const float* __restrict__ w_in,
                                               const float* __restrict__ b_in,
                                               const float* __restrict__ w_out,
                                               const float4* __restrict__ x4,
                                               const float* __restrict__ b_out,
                                               float4* __restrict__ out4,
                                               float* __restrict__ out,
                                               int out_size) {
    __shared__ float smf[KC], sgf[KC];
    __shared__ float sva[8], svb[8];
    __shared__ int   sia[8], sib[8];
    __shared__ int   scand[CCAP];
    __shared__ int   scnt;
    __shared__ float speakc;
    __shared__ int   sfcnt[FPC];
    __shared__ double swl[8];
    __shared__ int s_last;

    int cc = blockIdx.x;
    int t  = threadIdx.x;
    int w  = t >> 5, lane = t & 31;

    // ---------- Phase 0: issue pixel loads NOW (overlap table build) ----------
    int gid0 = cc * 512 + t;
    int gid1 = gid0 + 256;
    float4 xv0 = x4[gid0];
    float4 xv1 = x4[gid1];

    // ---------- Phase 1: lines (warp per line: 8 lines per block) ----------
    {
        int k = cc * 8 + w;
        const float* e = emb + k * DIMD;
        double a = 0.0, c = 0.0, s = 0.0, o = 0.0;
        #pragma unroll
        for (int d = lane; d < DIMD; d += 32) {
            double ed = (double)e[d];
            a += (double)w_in[d]  * ed;
            c += (double)b_in[d]  * ed;
            s += ed * ed;
            o += (double)w_out[d] * ed;
        }
        #pragma unroll
        for (int off = 16; off; off >>= 1) {
            a += __shfl_down_sync(0xFFFFFFFFu, a, off);
            c += __shfl_down_sync(0xFFFFFFFFu, c, off);
            s += __shfl_down_sync(0xFFFFFFFFu, s, off);
            o += __shfl_down_sync(0xFFFFFFFFu, o, off);
        }
        if (lane == 0) {
            double m = -2.0 * a, g = s - 2.0 * c;
            d_m[k] = m;  d_g[k] = g;
            d_mf[k] = (float)m;  d_gf[k] = (float)g;
            d_of[k] = (float)o;
        }
    }
    if (cc == 0 && w == 0) {
        double sw = 0.0, swb = 0.0, sb = 0.0;
        for (int d = lane; d < DIMD; d += 32) {
            double ww = (double)w_in[d], bb = (double)b_in[d];
            sw += ww * ww;  swb += ww * bb;  sb += bb * bb;
        }
        #pragma unroll
        for (int off = 16; off; off >>= 1) {
            sw  += __shfl_down_sync(0xFFFFFFFFu, sw,  off);
            swb += __shfl_down_sync(0xFFFFFFFFu, swb, off);
            sb  += __shfl_down_sync(0xFFFFFFFFu, sb,  off);
        }
        if (lane == 0) { d_Swf = (float)sw;  d_Swbf = (float)swb;  d_Sbf = (float)sb; }
    }

    grid_barrier_mono(&d_t1);

    // ---------- Phase 2: cell build ----------
    for (int j = t; j < KC; j += 256) { smf[j] = d_mf[j]; sgf[j] = d_gf[j]; }
    __syncthreads();

    double dxa = XLO + (double)cc * CWID - PADX;
    double dxb = XLO + (double)(cc + 1) * CWID + PADX;
    float xa = (float)dxa, xb = (float)dxb;

    float ba = INFINITY, bb = INFINITY;
    int ia = 0, ib = 0;
    #pragma unroll
    for (int j = t; j < KC; j += 256) {
        float m = smf[j], g = sgf[j];
        float va = fmaf(m, xa, g);
        float vb = fmaf(m, xb, g);
        if (va < ba) { ba = va; ia = j; }
        if (vb < bb) { bb = vb; ib = j; }
    }
    #pragma unroll
    for (int o = 16; o; o >>= 1) {
        float ova = __shfl_down_sync(0xFFFFFFFFu, ba, o);
        int   oia = __shfl_down_sync(0xFFFFFFFFu, ia, o);
        float ovb = __shfl_down_sync(0xFFFFFFFFu, bb, o);
        int   oib = __shfl_down_sync(0xFFFFFFFFu, ib, o);
        if (ova < ba) { ba = ova; ia = oia; }
        if (ovb < bb) { bb = ovb; ib = oib; }
    }
    if (lane == 0) { sva[w] = ba; sia[w] = ia; svb[w] = bb; sib[w] = ib; }
    __syncthreads();
    if (t < 8) {
        ba = sva[t]; ia = sia[t]; bb = svb[t]; ib = sib[t];
        #pragma unroll
        for (int o = 4; o; o >>= 1) {
            float ova = __shfl_down_sync(0xFFu, ba, o, 8);
            int   oia = __shfl_down_sync(0xFFu, ia, o, 8);
            float ovb = __shfl_down_sync(0xFFu, bb, o, 8);
            int   oib = __shfl_down_sync(0xFFu, ib, o, 8);
            if (ova < ba) { ba = ova; ia = oia; }
            if (ovb < bb) { bb = ovb; ib = oib; }
        }
        if (t == 0) {
            speakc = (float)wedge_peak(ia, ib, dxa, dxb) + EPSM;
            scnt = 0;
        }
    }
    __syncthreads();

    float pkc = speakc;
    #pragma unroll
    for (int j = t; j < KC; j += 256) {
        float m = smf[j], g = sgf[j];
        float vm = fminf(fmaf(m, xa, g), fmaf(m, xb, g));
        if (vm <= pkc) {
            int slot = atomicAdd(&scnt, 1);
            if (slot < CCAP) scand[slot] = j;
        }
    }
    __syncthreads();
    int ccnt = scnt;
    if (ccnt > CCAP) {
        if (t < FPC) {
            float4 fv; fv.x = 0.f; fv.y = 0.f; fv.z = 0.f;
            fv.w = __int_as_float(9999);
            d_fast[cc * FPC + t] = fv;
        }
    } else {
        if (t < FPC) sfcnt[t] = 0;
        __syncthreads();

        int j = t >> 2;           // fine cell 0..63
        int r = t & 3;            // 4 threads per fine cell
        int fcell = cc * FPC + j;
        double fxa = XLO + (double)fcell * FWID - PADX;
        double fxb = XLO + (double)(fcell + 1) * FWID + PADX;
        float fa = (float)fxa, fb = (float)fxb;

        float fba = INFINITY, fbb = INFINITY;
        int fia = 0, fib = 0;
        for (int i = r; i < ccnt; i += 4) {
            int k = scand[i];
            float m = smf[k], g = sgf[k];
            float va = fmaf(m, fa, g);
            float vb = fmaf(m, fb, g);
            if (va < fba) { fba = va; fia = k; }
            if (vb < fbb) { fbb = vb; fib = k; }
        }
        #pragma unroll
        for (int s = 2; s > 0; s >>= 1) {
            float ova = __shfl_down_sync(0xFFFFFFFFu, fba, s, 4);
            int   oia = __shfl_down_sync(0xFFFFFFFFu, fia, s, 4);
            float ovb = __shfl_down_sync(0xFFFFFFFFu, fbb, s, 4);
            int   oib = __shfl_down_sync(0xFFFFFFFFu, fib, s, 4);
            if (ova < fba) { fba = ova; fia = oia; }
            if (ovb < fbb) { fbb = ovb; fib = oib; }
        }
        float pkf;
        if (r == 0) pkf = (float)wedge_peak(fia, fib, fxa, fxb) + EPSM;
        pkf = __shfl_sync(0xFFFFFFFFu, pkf, lane & ~3, 32);

        for (int i = r; i < ccnt; i += 4) {
            int k = scand[i];
            float m = smf[k], g = sgf[k];
            float vm = fminf(fmaf(m, fa, g), fmaf(m, fb, g));
            if (vm <= pkf) {
                int slot = atomicAdd(&sfcnt[j], 1);
                if (slot < FCAP) d_cand[fcell * FCAP + slot] = k;
            }
        }
        __syncthreads();

        if (t < FPC) {
            int fc = cc * FPC + t;
            int cnt = sfcnt[t];
            float4 fv;
            if (cnt == 1) {
                int k = d_cand[fc * FCAP];
                fv.x = smf[k]; fv.y = sgf[k]; fv.z = d_of[k];
            } else { fv.x = 0.f; fv.y = 0.f; fv.z = 0.f; }
            fv.w = __int_as_float(cnt);
            d_fast[fc] = fv;
        }
    }

    grid_barrier_mono(&d_t2);

    // ---------- Phase 3: 8 pixels/thread, batched independent gathers ----------
    float bo = b_out[0];
    float Sw = d_Swf, Swb = d_Swbf, Sb = d_Sbf;
    double lsum = 0.0;

    float xs[8] = { xv0.x, xv0.y, xv0.z, xv0.w, xv1.x, xv1.y, xv1.z, xv1.w };

    int cells[8];
    #pragma unroll
    for (int l = 0; l < 8; ++l) {
        float rel = (xs[l] - (float)XLO) * (float)(1.0 / FWID);
        int c = (int)floorf(rel);
        cells[l] = ((unsigned)c < (unsigned)NFINE) ? c : -1;
    }
    float4 fv[8];
    #pragma unroll
    for (int l = 0; l < 8; ++l) {
        int c = (cells[l] >= 0) ? cells[l] : 0;
        fv[l] = d_fast[c];                  // 8 independent LDG.128
    }

    float res[8];
    #pragma unroll
    for (int l = 0; l < 8; ++l) {
        float x = xs[l];
        float bestf, oval;
        int cnt = (cells[l] >= 0) ? __float_as_int(fv[l].w) : 9999;
        if (cnt == 1) {
            bestf = fmaf(fv[l].x, x, fv[l].y);
            oval  = fv[l].z;
        } else if (cnt >= 2 && cnt <= FCAP) {
            double xd = (double)x;
            double best = 1e300;
            int bk = KC;
            int base = cells[l] * FCAP;
            for (int i = 0; i < cnt; ++i) {
                int k = d_cand[base + i];
                double v = fma(d_m[k], xd, d_g[k]);
                if (v < best || (v == best && k < bk)) { best = v; bk = k; }
            }
            bestf = (float)best;
            oval  = d_of[bk];
        } else {
            double xd = (double)x;
            double best = 1e300;
            int bk = KC;
            for (int k = 0; k < KC; ++k) {
                double v = fma(d_m[k], xd, d_g[k]);
                if (v < best) { best = v; bk = k; }
            }
            bestf = (float)best;
            oval  = d_of[bk];
        }
        res[l] = oval + bo;
        lsum += (double)(bestf + fmaf(x, fmaf(x, Sw, 2.0f * Swb), Sb));
    }
    float4 ov0, ov1;
    ov0.x = res[0]; ov0.y = res[1]; ov0.z = res[2]; ov0.w = res[3];
    ov1.x = res[4]; ov1.y = res[5]; ov1.z = res[6]; ov1.w = res[7];
    out4[gid0] = ov0;
    out4[gid1] = ov1;

    // ---------- Phase 4: loss reduction (shuffle, fixed order) ----------
    #pragma unroll
    for (int o = 16; o; o >>= 1) lsum += __shfl_down_sync(0xFFFFFFFFu, lsum, o);
    if (lane == 0) swl[w] = lsum;
    __syncthreads();
    if (t == 0) {
        double v2 = ((swl[0] + swl[1]) + (swl[2] + swl[3]))
                  + ((swl[4] + swl[5]) + (swl[6] + swl[7]));
        d_bsum[cc] = v2;
        __threadfence();
        unsigned dn = atomicAdd(&d_t3, 1);          // monotone ticket, no reset
        s_last = ((dn % NBLK) == NBLK - 1);
    }
    __syncthreads();

    if (s_last) {
        __threadfence();
        double lv = (t < NBLK) ? d_bsum[t] : 0.0;
        #pragma unroll
        for (int o = 16; o; o >>= 1) lv += __shfl_down_sync(0xFFFFFFFFu, lv, o);
        if (lane == 0) swl[w] = lv;
        __syncthreads();
        if (t == 0) {
            double tot = ((swl[0] + swl[1]) + (swl[2] + swl[3]))
                       + ((swl[4] + swl[5]) + (swl[6] + swl[7]));
            if (out_size > NPIX)
                out[NPIX] = (float)(12.5 * tot / ((double)NPIX * (double)DIMD));
        }
    }
}

extern "C" void kernel_launch(void* const* d_in, const int* in_sizes, int n_in,
                              void* d_out, int out_size) {
    const float* x     = (const float*)d_in[0];
    const float* w_in  = (const float*)d_in[1];
    const float* b_in  = (const float*)d_in[2];
    const float* emb   = (const float*)d_in[3];
    const float* w_out = (const float*)d_in[4];
    const float* b_out = (const float*)d_in[5];
    float* out = (float*)d_out;

    kAll<<<NBLK, 256>>>(emb, w_in, b_in, w_out,
                        (const float4*)x, b_out,
                        (float4*)out, out, out_size);
}

// round 11
// speedup vs baseline: 10.6112x; 10.6112x over previous
#include <cuda_runtime.h>
#include <math.h>

#define NPIX  262144      // 16*128*128
#define DIMD  64
#define KC    1024
#define NBLK  128         // 128 blocks x 256 threads x 8 px = NPIX
#define XLOF  (-8.0f)
#define NCC   64          // coarse cells over [-8,8], width 0.25
#define CWF   0.25f
#define NFC   512         // fine cells, width 0.03125
#define FWF   0.03125f
#define INVFW 32.0f
#define PADF  1e-4f
#define EPSF  2e-4f
#define CCAP  64
#define FCAP  12

// ---- device globals: loss partials + monotone last-block ticket (never reset) ----
__device__ double   d_bsum[NBLK];
__device__ unsigned d_done;

__global__ void __launch_bounds__(256) kAll(const float*  __restrict__ emb,
                                            const float*  __restrict__ w_in,
                                            const float*  __restrict__ b_in,
                                            const float*  __restrict__ w_out,
                                            const float4* __restrict__ x4,
                                            const float*  __restrict__ b_out,
                                            float4*       __restrict__ out4,
                                            float*        __restrict__ out,
                                            int out_size) {
    __shared__ float2 sm_mg[KC];            // (m, g) per code
    __shared__ float  sm_o[KC];             // o_k = e_k . w_out
    __shared__ float4 sm_w4[16], sm_b4[16], sm_wo4[16];
    __shared__ int    sm_ccnt[NCC];
    __shared__ short  sm_ccand[NCC][CCAP];
    __shared__ float4 sm_fast[NFC];         // (m, g, o, cnt-as-int)
    __shared__ short  sm_fcand[NFC][FCAP];
    __shared__ float  sm_quad[3];           // Sw, Swb, Sb
    __shared__ double swl[8];
    __shared__ int    s_last;

    int t = threadIdx.x, cc = blockIdx.x;
    int lane = t & 31, w = t >> 5;

    // ---- Phase 0: hoist pixel loads (overlap DRAM latency with table build) ----
    int gid0 = cc * 512 + t, gid1 = gid0 + 256;
    float4 xv0 = x4[gid0];
    float4 xv1 = x4[gid1];

    // ---- stage small vectors into smem ----
    if (t < 16) {
        sm_w4[t]  = ((const float4*)w_in)[t];
        sm_b4[t]  = ((const float4*)b_in)[t];
        sm_wo4[t] = ((const float4*)w_out)[t];
    }
    if (t < NCC) sm_ccnt[t] = 0;
    __syncthreads();

    // ---- quadratic loss coeffs (warp 0) ----
    if (w == 0) {
        float sw = 0.f, swb = 0.f, sb = 0.f;
        #pragma unroll
        for (int d = lane; d < DIMD; d += 32) {
            float ww = ((const float*)sm_w4)[d];
            float bb = ((const float*)sm_b4)[d];
            sw = fmaf(ww, ww, sw); swb = fmaf(ww, bb, swb); sb = fmaf(bb, bb, sb);
        }
        #pragma unroll
        for (int o = 16; o; o >>= 1) {
            sw  += __shfl_down_sync(0xFFFFFFFFu, sw,  o);
            swb += __shfl_down_sync(0xFFFFFFFFu, swb, o);
            sb  += __shfl_down_sync(0xFFFFFFFFu, sb,  o);
        }
        if (lane == 0) { sm_quad[0] = sw; sm_quad[1] = swb; sm_quad[2] = sb; }
    }

    // ---- Phase A: all 1024 lines, fp32, 4 rows/thread ----
    #pragma unroll
    for (int rr = 0; rr < 4; ++rr) {
        int row = t + rr * 256;
        const float4* e4 = (const float4*)(emb + row * DIMD);
        float a = 0.f, c = 0.f, s = 0.f, o = 0.f;
        #pragma unroll
        for (int i = 0; i < 16; ++i) {
            float4 e = e4[i];
            float4 wv = sm_w4[i], bv = sm_b4[i], ov = sm_wo4[i];
            a = fmaf(e.x, wv.x, a); a = fmaf(e.y, wv.y, a);
            a = fmaf(e.z, wv.z, a); a = fmaf(e.w, wv.w, a);
            c = fmaf(e.x, bv.x, c); c = fmaf(e.y, bv.y, c);
            c = fmaf(e.z, bv.z, c); c = fmaf(e.w, bv.w, c);
            s = fmaf(e.x, e.x, s);  s = fmaf(e.y, e.y, s);
            s = fmaf(e.z, e.z, s);  s = fmaf(e.w, e.w, s);
            o = fmaf(e.x, ov.x, o); o = fmaf(e.y, ov.y, o);
            o = fmaf(e.z, ov.z, o); o = fmaf(e.w, ov.w, o);
        }
        sm_mg[row] = make_float2(-2.f * a, s - 2.f * c);
        sm_o[row]  = o;
    }
    __syncthreads();

    // ---- Phase B1: coarse cells (4 threads per cell) ----
    int cel = t >> 2, r = t & 3;
    float xa = XLOF + (float)cel * CWF - PADF;
    float xb = xa + CWF + 2.f * PADF;
    float ba = 1e30f, bb2 = 1e30f;
    int ia = 0, ib = 0;
    for (int i = 0; i < 256; ++i) {
        int j = 4 * i + r;
        float2 mg = sm_mg[j];
        float va = fmaf(mg.x, xa, mg.y);
        float vb = fmaf(mg.x, xb, mg.y);
        if (va < ba)  { ba = va;  ia = j; }
        if (vb < bb2) { bb2 = vb; ib = j; }
    }
    #pragma unroll
    for (int o = 2; o; o >>= 1) {
        float ova = __shfl_down_sync(0xFFFFFFFFu, ba,  o, 4);
        int   oia = __shfl_down_sync(0xFFFFFFFFu, ia,  o, 4);
        float ovb = __shfl_down_sync(0xFFFFFFFFu, bb2, o, 4);
        int   oib = __shfl_down_sync(0xFFFFFFFFu, ib,  o, 4);
        if (ova < ba)  { ba = ova;  ia = oia; }
        if (ovb < bb2) { bb2 = ovb; ib = oib; }
    }
    float pk;
    if (r == 0) {
        // sound wedge-peak: envelope <= min(L_ia, L_ib); peak of wedge on [xa,xb]
        float2 m0 = sm_mg[ia], m1 = sm_mg[ib];
        float wa = fminf(fmaf(m0.x, xa, m0.y), fmaf(m1.x, xa, m1.y));
        float wb = fminf(fmaf(m0.x, xb, m0.y), fmaf(m1.x, xb, m1.y));
        pk = fmaxf(wa, wb);
        if (m0.x != m1.x) {
            float xc = (m1.y - m0.y) / (m0.x - m1.x);
            if (xc > xa && xc < xb) pk = fmaxf(pk, fmaf(m0.x, xc, m0.y));
        }
        pk += EPSF;
    }
    pk = __shfl_sync(0xFFFFFFFFu, pk, lane & ~3);
    for (int i = 0; i < 256; ++i) {
        int j = 4 * i + r;
        float2 mg = sm_mg[j];
        float vm = fminf(fmaf(mg.x, xa, mg.y), fmaf(mg.x, xb, mg.y));
        if (vm <= pk) {
            int slot = atomicAdd(&sm_ccnt[cel], 1);
            if (slot < CCAP) sm_ccand[cel][slot] = (short)j;
        }
    }
    __syncthreads();

    // ---- Phase B2: fine cells (2 per thread) ----
    #pragma unroll
    for (int ff = 0; ff < 2; ++ff) {
        int f = 2 * t + ff;
        int cc2 = f >> 3;
        int cnt = sm_ccnt[cc2];
        float4 fv;
        if (cnt > CCAP) {
            fv.x = 0.f; fv.y = 0.f; fv.z = 0.f; fv.w = __int_as_float(9999);
        } else {
            float fa = XLOF + (float)f * FWF - PADF;
            float fb = fa + FWF + 2.f * PADF;
            float b1 = 1e30f, b2 = 1e30f;
            int i1 = 0, i2 = 0;
            for (int i = 0; i < cnt; ++i) {
                int k = sm_ccand[cc2][i];
                float2 mg = sm_mg[k];
                float va = fmaf(mg.x, fa, mg.y);
                float vb = fmaf(mg.x, fb, mg.y);
                if (va < b1) { b1 = va; i1 = k; }
                if (vb < b2) { b2 = vb; i2 = k; }
            }
            float2 m0 = sm_mg[i1], m1 = sm_mg[i2];
            float wa = fminf(fmaf(m0.x, fa, m0.y), fmaf(m1.x, fa, m1.y));
            float wb = fminf(fmaf(m0.x, fb, m0.y), fmaf(m1.x, fb, m1.y));
            float pkf = fmaxf(wa, wb);
            if (m0.x != m1.x) {
                float xc = (m1.y - m0.y) / (m0.x - m1.x);
                if (xc > fa && xc < fb) pkf = fmaxf(pkf, fmaf(m0.x, xc, m0.y));
            }
            pkf += EPSF;
            int n = 0;
            for (int i = 0; i < cnt; ++i) {
                int k = sm_ccand[cc2][i];
                float2 mg = sm_mg[k];
                float vm = fminf(fmaf(mg.x, fa, mg.y), fmaf(mg.x, fb, mg.y));
                if (vm <= pkf) { if (n < FCAP) sm_fcand[f][n] = (short)k; n++; }
            }
            if (n == 1) {
                int k = sm_fcand[f][0];
                float2 mg = sm_mg[k];
                fv.x = mg.x; fv.y = mg.y; fv.z = sm_o[k]; fv.w = __int_as_float(1);
            } else {
                fv.x = 0.f; fv.y = 0.f; fv.z = 0.f;
                fv.w = __int_as_float(n <= FCAP ? n : 9999);
            }
        }
        sm_fast[f] = fv;
    }
    __syncthreads();

    // ---- Phase C: 8 pixels/thread from smem tables ----
    float bo = b_out[0];
    float Sw = sm_quad[0], Swb = sm_quad[1], Sb = sm_quad[2];
    double lsum = 0.0;
    float xs[8] = { xv0.x, xv0.y, xv0.z, xv0.w, xv1.x, xv1.y, xv1.z, xv1.w };
    float res[8];

    #pragma unroll
    for (int l = 0; l < 8; ++l) {
        float x = xs[l];
        float rel = (x - XLOF) * INVFW;
        int c = (int)floorf(rel);
        float bestf, oval;
        int cnt = ((unsigned)c < (unsigned)NFC) ? __float_as_int(sm_fast[c].w) : 9999;
        if (cnt == 1) {
            float4 fvv = sm_fast[c];
            bestf = fmaf(fvv.x, x, fvv.y);
            oval  = fvv.z;
        } else if (cnt >= 2 && cnt <= FCAP) {
            float best = 1e30f; int bk = KC;
            for (int i = 0; i < cnt; ++i) {
                int k = sm_fcand[c][i];
                float2 mg = sm_mg[k];
                float v = fmaf(mg.x, x, mg.y);
                if (v < best || (v == best && k < bk)) { best = v; bk = k; }
            }
            bestf = best; oval = sm_o[bk];
        } else {
            // exact fallback: full scan from smem (never expected for |x|<8)
            float best = 1e30f; int bk = KC;
            for (int k = 0; k < KC; ++k) {
                float2 mg = sm_mg[k];
                float v = fmaf(mg.x, x, mg.y);
                if (v < best) { best = v; bk = k; }
            }
            bestf = best; oval = sm_o[bk];
        }
        res[l] = oval + bo;
        lsum += (double)(bestf + fmaf(x, fmaf(x, Sw, 2.f * Swb), Sb));
    }
    float4 ov0, ov1;
    ov0.x = res[0]; ov0.y = res[1]; ov0.z = res[2]; ov0.w = res[3];
    ov1.x = res[4]; ov1.y = res[5]; ov1.z = res[6]; ov1.w = res[7];
    out4[gid0] = ov0;
    out4[gid1] = ov1;

    // ---- Phase D: loss reduction; last block (monotone ticket, NO spin) ----
    #pragma unroll
    for (int o = 16; o; o >>= 1) lsum += __shfl_down_sync(0xFFFFFFFFu, lsum, o);
    if (lane == 0) swl[w] = lsum;
    __syncthreads();
    if (t == 0) {
        double v2 = ((swl[0] + swl[1]) + (swl[2] + swl[3]))
                  + ((swl[4] + swl[5]) + (swl[6] + swl[7]));
        d_bsum[cc] = v2;
        __threadfence();
        unsigned dn = atomicAdd(&d_done, 1);        // monotone; 2^32 % 128 == 0
        s_last = ((dn % NBLK) == NBLK - 1);
    }
    __syncthreads();

    if (s_last) {
        __threadfence();
        double lv = (t < NBLK) ? d_bsum[t] : 0.0;
        #pragma unroll
        for (int o = 16; o; o >>= 1) lv += __shfl_down_sync(0xFFFFFFFFu, lv, o);
        if (lane == 0) swl[w] = lv;
        __syncthreads();
        if (t == 0) {
            double tot = ((swl[0] + swl[1]) + (swl[2] + swl[3]))
                       + ((swl[4] + swl[5]) + (swl[6] + swl[7]));
            if (out_size > NPIX)
                out[NPIX] = (float)(12.5 * tot / ((double)NPIX * (double)DIMD));
        }
    }
}

extern "C" void kernel_launch(void* const* d_in, const int* in_sizes, int n_in,
                              void* d_out, int out_size) {
    const float* x     = (const float*)d_in[0];
    const float* w_in  = (const float*)d_in[1];
    const float* b_in  = (const float*)d_in[2];
    const float* emb   = (const float*)d_in[3];
    const float* w_out = (const float*)d_in[4];
    const float* b_out = (const float*)d_in[5];
    float* out = (float*)d_out;

    kAll<<<NBLK, 256>>>(emb, w_in, b_in, w_out,
                        (const float4*)x, b_out,
                        (float4*)out, out, out_size);
}

// round 15
// speedup vs baseline: 51.8105x; 4.8826x over previous
#include <cuda_runtime.h>
#include <math.h>

#define NPIX 262144      // 16*128*128
#define DIMD 64
#define KC   1024
#define NFINE 8192
#define NCOARSE 256
#define FPC   (NFINE / NCOARSE)      // 32 fine cells per coarse cell
#define XLO  (-12.0f)
#define CWIDF (24.0f / (float)NCOARSE)
#define FWIDF (24.0f / (float)NFINE)
#define INVFW ((float)NFINE / 24.0f)
#define PADX (1e-4f)
#define EPSM (1e-4f)
#define CCAP 64
#define FCAP 8
#define NBLKB 128                    // kB: 128 blocks * 256 threads * 8 px = NPIX

// ---- scratch (__device__ globals; zero-initialized at module load) ----
__device__ float  d_mf[KC], d_gf[KC];        // line slope/intercept (fp32)
__device__ float  d_of[KC];                  // o_k = emb_k . w_out
__device__ float  d_Swf, d_Swbf, d_Sbf;      // loss-quadratic coeffs
__device__ int    d_cand[NFINE * FCAP];      // slow-path candidate lists (cnt>=3)
__device__ float4 d_fast[NFINE];             // (m0, g0, o0, cnt-as-int)
__device__ float4 d_fast2[NFINE];            // (m1, g1, o1, -) ; ==fast when cnt==1
__device__ double d_bsum[NBLKB];
__device__ volatile unsigned d_barA;         // kA grid barrier (reset by kB)
__device__ unsigned d_doneB;                 // kB last-block counter (reset by kA)

// Sound wedge-peak bound over [xa,xb] (fp32): envelope <= min(L0,L1);
// peak of that wedge = max(endpoint mins, crossing if inside).
__device__ __forceinline__ float wedge_peak_f(float2 L0, float2 L1, float xa, float xb) {
    float wa = fminf(fmaf(L0.x, xa, L0.y), fmaf(L1.x, xa, L1.y));
    float wb = fminf(fmaf(L0.x, xb, L0.y), fmaf(L1.x, xb, L1.y));
    float pk = fmaxf(wa, wb);
    if (L0.x != L1.x) {
        float xc = (L1.y - L0.y) / (L0.x - L1.x);
        if (xc > xa && xc < xb) pk = fmaxf(pk, fmaf(L0.x, xc, L0.y));
    }
    return pk;
}

// ================= kA: lines + grid barrier + cell build =================
__global__ void __launch_bounds__(256) kA(const float* __restrict__ emb,
                                          const float* __restrict__ w_in,
                                          const float* __restrict__ b_in,
                                          const float* __restrict__ w_out) {
    __shared__ float smf[KC], sgf[KC];
    __shared__ float sva[256], svb[256];
    __shared__ int   sia[256], sib[256];
    __shared__ int   scand[CCAP];
    __shared__ int   scnt;
    __shared__ float speakc;
    __shared__ int   sfcnt[FPC];

    int cc = blockIdx.x;
    int t  = threadIdx.x;

    if (cc == 0 && t == 0) d_doneB = 0;   // arm kB's last-block counter

    // --- Phase 1: threads 0-3 compute lines cc*4 .. cc*4+3 (fp32, float4) ---
    if (t < 4) {
        int k = cc * 4 + t;
        const float4* e4 = (const float4*)(emb + k * DIMD);
        const float4* w4 = (const float4*)w_in;
        const float4* b4 = (const float4*)b_in;
        const float4* o4 = (const float4*)w_out;
        float a = 0.f, c = 0.f, s = 0.f, o = 0.f;
        #pragma unroll
        for (int i = 0; i < 16; ++i) {
            float4 e = e4[i], wv = w4[i], bv = b4[i], ov = o4[i];
            a = fmaf(e.x, wv.x, a); a = fmaf(e.y, wv.y, a);
            a = fmaf(e.z, wv.z, a); a = fmaf(e.w, wv.w, a);
            c = fmaf(e.x, bv.x, c); c = fmaf(e.y, bv.y, c);
            c = fmaf(e.z, bv.z, c); c = fmaf(e.w, bv.w, c);
            s = fmaf(e.x, e.x, s);  s = fmaf(e.y, e.y, s);
            s = fmaf(e.z, e.z, s);  s = fmaf(e.w, e.w, s);
            o = fmaf(e.x, ov.x, o); o = fmaf(e.y, ov.y, o);
            o = fmaf(e.z, ov.z, o); o = fmaf(e.w, ov.w, o);
        }
        d_mf[k] = -2.f * a;
        d_gf[k] = s - 2.f * c;
        d_of[k] = o;
    } else if (cc == 0 && t == 4) {
        float sw = 0.f, swb = 0.f, sb = 0.f;
        for (int d = 0; d < DIMD; ++d) {
            float ww = w_in[d], bb = b_in[d];
            sw = fmaf(ww, ww, sw); swb = fmaf(ww, bb, swb); sb = fmaf(bb, bb, sb);
        }
        d_Swf = sw; d_Swbf = swb; d_Sbf = sb;
    }
    __syncthreads();

    // --- software grid barrier (256 blocks co-resident; proven pattern) ---
    if (t == 0) {
        __threadfence();
        atomicAdd((unsigned*)&d_barA, 1);
        while (d_barA < NCOARSE) { }
        __threadfence();
    }
    __syncthreads();

    // --- load all lines into smem ---
    for (int j = t; j < KC; j += 256) { smf[j] = d_mf[j]; sgf[j] = d_gf[j]; }
    __syncthreads();

    // --- Phase A: coarse cell endpoint argmin ---
    float xa = XLO + (float)cc * CWIDF - PADX;
    float xb = xa + CWIDF + 2.f * PADX;

    float ba = 1e30f, bb = 1e30f;
    int ia = 0, ib = 0;
    #pragma unroll
    for (int j = t; j < KC; j += 256) {
        float m = smf[j], g = sgf[j];
        float va = fmaf(m, xa, g);
        float vb = fmaf(m, xb, g);
        if (va < ba) { ba = va; ia = j; }
        if (vb < bb) { bb = vb; ib = j; }
    }
    sva[t] = ba; sia[t] = ia; svb[t] = bb; sib[t] = ib;
    __syncthreads();
    for (int s = 128; s > 0; s >>= 1) {
        if (t < s) {
            if (sva[t + s] < sva[t]) { sva[t] = sva[t + s]; sia[t] = sia[t + s]; }
            if (svb[t + s] < svb[t]) { svb[t] = svb[t + s]; sib[t] = sib[t + s]; }
        }
        __syncthreads();
    }
    if (t == 0) {
        float2 L0 = make_float2(smf[sia[0]], sgf[sia[0]]);
        float2 L1 = make_float2(smf[sib[0]], sgf[sib[0]]);
        speakc = wedge_peak_f(L0, L1, xa, xb) + EPSM;
        scnt = 0;
    }
    __syncthreads();

    // --- Phase A2: collect coarse candidates ---
    float pkc = speakc;
    #pragma unroll
    for (int j = t; j < KC; j += 256) {
        float m = smf[j], g = sgf[j];
        float vm = fminf(fmaf(m, xa, g), fmaf(m, xb, g));
        if (vm <= pkc) {
            int slot = atomicAdd(&scnt, 1);
            if (slot < CCAP) scand[slot] = j;
        }
    }
    __syncthreads();
    int ccnt = scnt;
    if (ccnt > CCAP) {
        // overflow: flag fine cells for full fallback (practically never)
        if (t < FPC) {
            float4 fv; fv.x = 0.f; fv.y = 0.f; fv.z = 0.f;
            fv.w = __int_as_float(9999);
            d_fast[cc * FPC + t] = fv;
            d_fast2[cc * FPC + t] = fv;
        }
        return;
    }
    if (t < FPC) sfcnt[t] = 0;
    __syncthreads();

    // --- Phase B: fine cells. 8 threads (r) per fine cell (j). ---
    int j = t >> 3;
    int r = t & 7;
    int fcell = cc * FPC + j;
    float fa = XLO + (float)fcell * FWIDF - PADX;
    float fb = fa + FWIDF + 2.f * PADX;

    float fba = 1e30f, fbb = 1e30f;
    int fia = 0, fib = 0;
    for (int i = r; i < ccnt; i += 8) {
        int k = scand[i];
        float m = smf[k], g = sgf[k];
        float va = fmaf(m, fa, g);
        float vb = fmaf(m, fb, g);
        if (va < fba) { fba = va; fia = k; }
        if (vb < fbb) { fbb = vb; fib = k; }
    }
    #pragma unroll
    for (int s = 4; s > 0; s >>= 1) {
        float ova = __shfl_down_sync(0xFFFFFFFFu, fba, s, 8);
        int   oia = __shfl_down_sync(0xFFFFFFFFu, fia, s, 8);
        float ovb = __shfl_down_sync(0xFFFFFFFFu, fbb, s, 8);
        int   oib = __shfl_down_sync(0xFFFFFFFFu, fib, s, 8);
        if (ova < fba) { fba = ova; fia = oia; }
        if (ovb < fbb) { fbb = ovb; fib = oib; }
    }
    float pkf;
    if (r == 0) {
        float2 L0 = make_float2(smf[fia], sgf[fia]);
        float2 L1 = make_float2(smf[fib], sgf[fib]);
        pkf = wedge_peak_f(L0, L1, fa, fb) + EPSM;
    }
    pkf = __shfl_sync(0xFFFFFFFFu, pkf, (t & ~7) & 31, 32);

    for (int i = r; i < ccnt; i += 8) {
        int k = scand[i];
        float m = smf[k], g = sgf[k];
        float vm = fminf(fmaf(m, fa, g), fmaf(m, fb, g));
        if (vm <= pkf) {
            int slot = atomicAdd(&sfcnt[j], 1);
            if (slot < FCAP) d_cand[fcell * FCAP + slot] = k;
        }
    }
    __syncthreads();

    // --- write fast tables (one thread per fine cell) ---
    if (t < FPC) {
        int fc = cc * FPC + t;
        int cnt = sfcnt[t];
        float4 fv, fv2;
        if (cnt == 1) {
            int k = d_cand[fc * FCAP];
            fv.x = smf[k]; fv.y = sgf[k]; fv.z = d_of[k];
            fv.w = __int_as_float(1);
            fv2 = fv;                        // duplicate: branchless min is a no-op
        } else if (cnt == 2) {
            int k0 = d_cand[fc * FCAP], k1 = d_cand[fc * FCAP + 1];
            if (k1 < k0) { int tmp = k0; k0 = k1; k1 = tmp; }  // deterministic order
            fv.x  = smf[k0]; fv.y  = sgf[k0]; fv.z  = d_of[k0];
            fv.w  = __int_as_float(2);
            fv2.x = smf[k1]; fv2.y = sgf[k1]; fv2.z = d_of[k1];
            fv2.w = 0.f;
        } else {
            fv.x = 0.f; fv.y = 0.f; fv.z = 0.f;
            fv.w = __int_as_float(cnt);      // 0 impossible; 3..FCAP slow; >FCAP full
            fv2 = fv;
        }
        d_fast[fc]  = fv;
        d_fast2[fc] = fv2;
    }
}

// ================= kB: 8 px/thread, branchless 2-entry fast path =================
__global__ void __launch_bounds__(256) kB(const float4* __restrict__ x4,
                                          const float* __restrict__ b_out,
                                          float4* __restrict__ out4,
                                          float* __restrict__ out,
                                          int out_size) {
    __shared__ double swl[8];
    __shared__ int s_last;
    if (blockIdx.x == 0 && threadIdx.x == 0) d_barA = 0;   // re-arm kA's barrier

    int t = threadIdx.x;
    int w = t >> 5, lane = t & 31;
    int gid0 = blockIdx.x * 512 + t;
    int gid1 = gid0 + 256;

    float4 xv0 = x4[gid0];                 // issued immediately (MLP)
    float4 xv1 = x4[gid1];
    float bo = b_out[0];
    float Sw = d_Swf, Swb = d_Swbf, Sb = d_Sbf;

    float xs[8] = { xv0.x, xv0.y, xv0.z, xv0.w, xv1.x, xv1.y, xv1.z, xv1.w };

    int cells[8];
    #pragma unroll
    for (int l = 0; l < 8; ++l) {
        float rel = (xs[l] - XLO) * INVFW;
        int c = (int)floorf(rel);
        cells[l] = ((unsigned)c < (unsigned)NFINE) ? c : -1;
    }
    float4 f1[8], f2[8];
    #pragma unroll
    for (int l = 0; l < 8; ++l) {
        int c = (cells[l] >= 0) ? cells[l] : 0;
        f1[l] = d_fast[c];                  // 16 independent LDG.128
        f2[l] = d_fast2[c];
    }

    double lsum = 0.0;
    float res[8];
    #pragma unroll
    for (int l = 0; l < 8; ++l) {
        float x = xs[l];
        float bestf, oval;
        int cnt = (cells[l] >= 0) ? __float_as_int(f1[l].w) : 9999;
        if (cnt <= 2) {
            // branchless 2-line min; strict < keeps lower-index winner on ties
            float v0 = fmaf(f1[l].x, x, f1[l].y);
            float v1 = fmaf(f2[l].x, x, f2[l].y);
            bool sel = (v1 < v0);
            bestf = sel ? v1 : v0;
            oval  = sel ? f2[l].z : f1[l].z;
        } else if (cnt <= FCAP) {
            float best = 1e30f; int bk = KC;
            int base = cells[l] * FCAP;
            for (int i = 0; i < cnt; ++i) {
                int k = d_cand[base + i];
                float v = fmaf(d_mf[k], x, d_gf[k]);
                if (v < best || (v == best && k < bk)) { best = v; bk = k; }
            }
            bestf = best; oval = d_of[bk];
        } else {
            // exact fallback: full scan (never expected for |x| < 12)
            float best = 1e30f; int bk = KC;
            for (int k = 0; k < KC; ++k) {
                float v = fmaf(d_mf[k], x, d_gf[k]);
                if (v < best) { best = v; bk = k; }
            }
            bestf = best; oval = d_of[bk];
        }
        res[l] = oval + bo;
        lsum += (double)(bestf + fmaf(x, fmaf(x, Sw, 2.0f * Swb), Sb));
    }
    float4 ov0, ov1;
    ov0.x = res[0]; ov0.y = res[1]; ov0.z = res[2]; ov0.w = res[3];
    ov1.x = res[4]; ov1.y = res[5]; ov1.z = res[6]; ov1.w = res[7];
    out4[gid0] = ov0;
    out4[gid1] = ov1;

    // ---- per-block loss reduction (shuffle, fixed order) ----
    #pragma unroll
    for (int o = 16; o; o >>= 1) lsum += __shfl_down_sync(0xFFFFFFFFu, lsum, o);
    if (lane == 0) swl[w] = lsum;
    __syncthreads();
    if (t == 0) {
        double v2 = ((swl[0] + swl[1]) + (swl[2] + swl[3]))
                  + ((swl[4] + swl[5]) + (swl[6] + swl[7]));
        d_bsum[blockIdx.x] = v2;
        __threadfence();
        unsigned dn = atomicAdd(&d_doneB, 1);
        s_last = (dn == NBLKB - 1);
    }
    __syncthreads();

    if (s_last) {
        __threadfence();
        double lv = (t < NBLKB) ? d_bsum[t] : 0.0;
        #pragma unroll
        for (int o = 16; o; o >>= 1) lv += __shfl_down_sync(0xFFFFFFFFu, lv, o);
        if (lane == 0) swl[w] = lv;
        __syncthreads();
        if (t == 0) {
            double tot = ((swl[0] + swl[1]) + (swl[2] + swl[3]))
                       + ((swl[4] + swl[5]) + (swl[6] + swl[7]));
            if (out_size > NPIX)
                out[NPIX] = (float)(12.5 * tot / ((double)NPIX * (double)DIMD));
        }
    }
}

extern "C" void kernel_launch(void* const* d_in, const int* in_sizes, int n_in,
                              void* d_out, int out_size) {
    const float* x     = (const float*)d_in[0];
    const float* w_in  = (const float*)d_in[1];
    const float* b_in  = (const float*)d_in[2];
    const float* emb   = (const float*)d_in[3];
    const float* w_out = (const float*)d_in[4];
    const float* b_out = (const float*)d_in[5];
    float* out = (float*)d_out;

    kA<<<NCOARSE, 256>>>(emb, w_in, b_in, w_out);
    kB<<<NBLKB, 256>>>((const float4*)x, b_out, (float4*)out, out, out_size);
}